// round 12
// baseline (speedup 1.0000x reference)
#include <cuda_runtime.h>
#include <math.h>

#define N_SAMPLES 131072
#define N_EVENTS  128
#define N_ATOMS   32
#define ATOM_SIZE 512
#define LATENT    16
#define TIME_DIM  17
#define LAYERS    7

// ---------------- device-global scratch (no allocation allowed) ----------------
__device__ float g_xf[N_EVENTS * LATENT];            // final latent per event
__device__ int   g_pos[N_EVENTS];                    // dirac shift per event
__device__ float g_wave[N_EVENTS * ATOM_SIZE];       // pre-scaled waveforms
__device__ int   g_tree_done;                        // flag: tree outputs ready
__device__ int   g_wave_done;                        // counter: waves completed

// 16-term dot product, serial FMA chain in ascending index order.
// EXACTLY the same association order as all prior passing kernels so the
// argmax bit decisions are bit-identical.
__device__ __forceinline__ float dot16(float4 w0, float4 w1, float4 w2, float4 w3,
                                       float4 x0, float4 x1, float4 x2, float4 x3,
                                       float init)
{
    float v = init;
    v = fmaf(x0.x, w0.x, v); v = fmaf(x0.y, w0.y, v);
    v = fmaf(x0.z, w0.z, v); v = fmaf(x0.w, w0.w, v);
    v = fmaf(x1.x, w1.x, v); v = fmaf(x1.y, w1.y, v);
    v = fmaf(x1.z, w1.z, v); v = fmaf(x1.w, w1.w, v);
    v = fmaf(x2.x, w2.x, v); v = fmaf(x2.y, w2.y, v);
    v = fmaf(x2.z, w2.z, v); v = fmaf(x2.w, w2.w, v);
    v = fmaf(x3.x, w3.x, v); v = fmaf(x3.y, w3.y, v);
    v = fmaf(x3.z, w3.z, v); v = fmaf(x3.w, w3.w, v);
    return v;
}

// sizes
#define WT_ELEMS (LAYERS * 68 * LATENT)   // 7616
#define WS_ELEMS (LAYERS * 32 * LATENT)   // 3584
#define BS_ELEMS (LAYERS * 32)            // 224
#define X_ELEMS  (N_EVENTS * LATENT)      // 2048
#define T_ELEMS  (N_EVENTS * 34)          // 4352
#define TREE_SMEM_FLOATS (2 * X_ELEMS + 2 * T_ELEMS)   // 12800 floats = 51.2 KB

// -------------- K0: per-call flag reset (determinism across graph replays) ----
__global__ void reset_kernel()
{
    g_tree_done = 0;
    g_wave_done = 0;
}

// ---------------- K1: fused tree + wave + gather -------------------------------
// grid = 128 blocks x 512 threads. Block 0 additionally runs the tree first.
// Liveness needs only all 128 blocks resident (32 SMs at 4 CTA/SM).
__global__ __launch_bounds__(512, 2)
void fused_kernel(const float* __restrict__ base_latent,
                  const float* __restrict__ Wt,      // (7, 68, 16)
                  const float* __restrict__ Ws,      // (7, 32, 16)
                  const float* __restrict__ bs,      // (7, 32)
                  const float* __restrict__ atoms,   // (32, 512)
                  const float* __restrict__ Wa,      // (32, 16)
                  const float* __restrict__ ba,      // (32,)
                  const float* __restrict__ Wamp,    // (1, 16)
                  const float* __restrict__ bamp,    // (1,)
                  float* __restrict__ out)
{
    extern __shared__ float sm[];                // 51.2 KB (tree uses it in block 0)
    __shared__ float cs[N_ATOMS];
    __shared__ float s_amp;
    __shared__ float s_red[16];
    __shared__ int   ps[N_EVENTS];

    const int b   = blockIdx.x;
    const int tid = threadIdx.x;                 // 512 threads

    // =================== TREE (block 0 only) ===================
    if (b == 0) {
        float* sx = sm;                          // 2 * 2048  ping-pong latent
        float* st = sm + 2 * X_ELEMS;            // 2 * 4352  ping-pong times

        const int r = tid & 127;                 // row lane
        const int g = tid >> 7;                  // event group (0..3)

        if (tid < LATENT)       sx[tid] = base_latent[tid];
        if (tid < TIME_DIM * 2) st[tid] = 0.0f;
        __syncthreads();

        const bool is_time = (r < 68);
        const bool is_lat  = (r >= 68) && (r < 100);
        const int  c  = r / 34;                  // time: child index
        const int  rr = r - c * 34;              // time: (t*2 + s)
        const int  jl = r - 68;                  // latent row
        const int  ch = jl >> 4;                 // latent: child index
        const int  sl = jl & 15;                 // latent: slot

        for (int i = 0; i < LAYERS; i++) {
            // weight row for this layer -> registers (coalesced)
            float4 w0 = {0,0,0,0}, w1 = {0,0,0,0}, w2 = {0,0,0,0}, w3 = {0,0,0,0};
            float  bias = 0.0f;
            if (is_time) {
                const float4* wp = (const float4*)(Wt + (size_t)(i * 68 + r) * LATENT);
                w0 = wp[0]; w1 = wp[1]; w2 = wp[2]; w3 = wp[3];
            } else if (is_lat) {
                const float4* wp = (const float4*)(Ws + (size_t)(i * 32 + jl) * LATENT);
                w0 = wp[0]; w1 = wp[1]; w2 = wp[2]; w3 = wp[3];
                bias = bs[i * 32 + jl];
            }

            const int n = 1 << i;
            const float* xA = sx + (i & 1) * X_ELEMS;
            float*       xB = sx + ((i & 1) ^ 1) * X_ELEMS;
            const float* tA = st + (i & 1) * T_ELEMS;
            float*       tB = st + ((i & 1) ^ 1) * T_ELEMS;

            if (is_time) {
                for (int e = g; e < n; e += 4) {
                    const float4* xp = (const float4*)(xA + e * LATENT);  // broadcast
                    const float4 x0 = xp[0], x1 = xp[1], x2 = xp[2], x3 = xp[3];
                    const float v = dot16(w0, w1, w2, w3, x0, x1, x2, x3, 0.0f);
                    tB[(2 * e + c) * 34 + rr] = tA[e * 34 + rr] + v;
                }
            } else if (is_lat) {
                for (int e = g; e < n; e += 4) {
                    const float4* xp = (const float4*)(xA + e * LATENT);  // broadcast
                    const float4 x0 = xp[0], x1 = xp[1], x2 = xp[2], x3 = xp[3];
                    const float v = dot16(w0, w1, w2, w3, x0, x1, x2, x3, bias);
                    xB[(2 * e + ch) * LATENT + sl] = v;
                }
            }
            __syncthreads();
        }

        // LAYERS = 7 (odd) -> final buffers in parity 1
        const float* xF = sx + X_ELEMS;
        const float* tF = st + T_ELEMS;

        for (int k = tid; k < X_ELEMS; k += 512) g_xf[k] = xF[k];

        if (tid < N_EVENTS) {
            const int e = tid;
            int p = 0;
            #pragma unroll
            for (int t = 0; t < TIME_DIM; t++) {
                const int bit = tF[e * 34 + t * 2 + 1] > tF[e * 34 + t * 2 + 0];
                p |= bit << (TIME_DIM - 1 - t);
            }
            g_pos[e] = p;
        }

        __threadfence();        // publish g_xf / g_pos
        __syncthreads();
        if (tid == 0) atomicExch(&g_tree_done, 1);   // release
    }

    // =================== WAVE (every block: event e = b) ===================
    if (tid == 0) {
        while (*((volatile int*)&g_tree_done) == 0) __nanosleep(64);
        __threadfence();        // acquire
    }
    __syncthreads();

    {
        const int e = b;
        const float* xe = g_xf + e * LATENT;

        if (tid < N_ATOMS) {
            float v = ba[tid];
            #pragma unroll
            for (int d = 0; d < LATENT; d++) v += xe[d] * Wa[tid * LATENT + d];
            cs[tid] = v;
        }
        if (tid == N_ATOMS) {
            float v = bamp[0];
            #pragma unroll
            for (int d = 0; d < LATENT; d++) v += xe[d] * Wamp[d];
            s_amp = v;
        }
        __syncthreads();

        // sample j = tid (512 threads, one per sample)
        float v = 0.0f;
        #pragma unroll
        for (int k = 0; k < N_ATOMS; k++) v += cs[k] * atoms[k * ATOM_SIZE + tid];
        // Hamming window: 0.54 - 0.46*cos(2*pi*j/512)
        const float win = 0.54f - 0.46f * cospif((float)tid * (1.0f / 256.0f));
        v *= win;

        // block reduce sum of squares (16 warps)
        float sq = v * v;
        #pragma unroll
        for (int o = 16; o > 0; o >>= 1) sq += __shfl_xor_sync(0xffffffffu, sq, o);
        if ((tid & 31) == 0) s_red[tid >> 5] = sq;
        __syncthreads();
        float tot = s_red[0];
        #pragma unroll
        for (int w = 1; w < 16; w++) tot += s_red[w];
        const float scale = s_amp / (sqrtf(tot) + 1e-8f);

        g_wave[e * ATOM_SIZE + tid] = v * scale;

        __threadfence();        // publish this wave
        __syncthreads();
        if (tid == 0) atomicAdd(&g_wave_done, 1);    // release
    }

    // =================== GATHER (every block: tiles 2b, 2b+1) ===================
    if (tid == 0) {
        while (*((volatile int*)&g_wave_done) < N_EVENTS) __nanosleep(64);
        __threadfence();        // acquire
    }
    __syncthreads();

    if (tid < N_EVENTS) ps[tid] = g_pos[tid];
    __syncthreads();

    #pragma unroll
    for (int q = 0; q < 2; q++) {
        const int t0 = (2 * b + q) * ATOM_SIZE;
        const int t  = t0 + tid;

        float acc = 0.0f;
        // fixed event order -> bit-deterministic float accumulation (no atomics)
        #pragma unroll 4
        for (int e = 0; e < N_EVENTS; e++) {
            const int p = ps[e];
            if (p < t0 + ATOM_SIZE && p + ATOM_SIZE > t0) {
                const unsigned off = (unsigned)(t - p);
                if (off < (unsigned)ATOM_SIZE) acc += g_wave[e * ATOM_SIZE + off];
            }
        }
        out[t] = acc;
    }
}

// ---------------- launch -------------------------------------------------------
extern "C" void kernel_launch(void* const* d_in, const int* in_sizes, int n_in,
                              void* d_out, int out_size)
{
    // Robust input mapping by element count (all sizes unique except the two 16s,
    // where dict order gives base_latent before to_amp_W).
    const float *base_latent = nullptr, *Wt = nullptr, *Ws = nullptr, *bs = nullptr;
    const float *atoms = nullptr, *Wa = nullptr, *ba = nullptr, *Wamp = nullptr, *bamp = nullptr;
    for (int i = 0; i < n_in; i++) {
        const int s = in_sizes[i];
        const float* p = (const float*)d_in[i];
        switch (s) {
            case WT_ELEMS:              Wt = p;    break;   // 7616
            case WS_ELEMS:              Ws = p;    break;   // 3584
            case BS_ELEMS:              bs = p;    break;   // 224
            case N_ATOMS * ATOM_SIZE:   atoms = p; break;   // 16384
            case N_ATOMS * LATENT:      Wa = p;    break;   // 512
            case N_ATOMS:               ba = p;    break;   // 32
            case 1:                     bamp = p;  break;   // 1
            case LATENT:                                    // 16, twice
                if (!base_latent) base_latent = p; else Wamp = p;
                break;
            default: break;
        }
    }

    float* out = (float*)d_out;

    const int tree_smem = TREE_SMEM_FLOATS * (int)sizeof(float);   // 51.2 KB
    cudaFuncSetAttribute(fused_kernel, cudaFuncAttributeMaxDynamicSharedMemorySize, tree_smem);

    reset_kernel<<<1, 1>>>();
    fused_kernel<<<N_EVENTS, 512, tree_smem>>>(base_latent, Wt, Ws, bs,
                                               atoms, Wa, ba, Wamp, bamp, out);
    (void)out_size;
}